// round 1
// baseline (speedup 1.0000x reference)
#include <cuda_runtime.h>

#define BB 512
#define TT 128
#define FF 256
#define HH 384
#define LL 3
#define KW 10
#define LAB 25
#define CHN 128
#define GATES 1542
#define HID 64

// ---------------- device scratch ----------------
__device__ __align__(16) int   g_perm[BB];
__device__ __align__(16) int   g_vlen[BB];
__device__ __align__(16) int   g_nact[TT];
__device__ __align__(16) float g_pre[(size_t)TT * BB * GATES];   // 404 MB
__device__ __align__(16) float g_xo[BB * GATES];
__device__ __align__(16) float g_h[BB * HH];
__device__ __align__(16) float g_c[BB * HH];
__device__ __align__(16) float g_tmph[KW * BB * HH];
__device__ __align__(16) float g_tmpdis[KW * BB];
__device__ __align__(16) float g_convT[HH * KW * HH];            // [(hh*KW+k)*H + o]

// ---------------- setup: stable counting sort by v_len descending ----------------
__global__ void k_setup(const int* __restrict__ vlen) {
    int cnt[129];
    for (int v = 0; v <= 128; v++) cnt[v] = 0;
    for (int b = 0; b < BB; b++) cnt[vlen[b]]++;
    int cur[129];
    int off = 0;
    for (int v = 128; v >= 1; v--) { cur[v] = off; off += cnt[v]; }
    for (int b = 0; b < BB; b++) {
        int v = vlen[b];
        int p = cur[v]++;
        g_perm[p] = b;
        g_vlen[p] = v;
    }
    int suf = 0;
    for (int t = TT - 1; t >= 0; t--) { suf += cnt[t + 1]; g_nact[t] = suf; }
}

__global__ void k_zero() {
    int i = blockIdx.x * blockDim.x + threadIdx.x;
    if (i < BB * HH) { g_h[i] = 0.f; g_c[i] = 0.f; }
    if (i < KW * BB * HH) g_tmph[i] = 0.f;
    if (i < KW * BB) g_tmpdis[i] = 0.f;
}

__global__ void k_convT(const float* __restrict__ cw) {
    int i = blockIdx.x * blockDim.x + threadIdx.x;
    if (i >= HH * HH * KW) return;
    int k  = i % KW;
    int hh = (i / KW) % HH;
    int o  = i / (KW * HH);
    g_convT[(hh * KW + k) * HH + o] = cw[i];
}

// ---------------- precompute GEMM: PRE[t,p,:] = X[perm[p],t,:] @ kw + biases ----------------
// grid: (25 gate-tiles, 1024 row-tiles of 64); row-tile = (p, t0 in {0,64})
__global__ void k_gemm_pre(const float* __restrict__ X, const float* __restrict__ kw,
                           const float* __restrict__ kb, const float* __restrict__ rw,
                           const float* __restrict__ rb) {
    __shared__ float As[16][68];
    __shared__ float Bs[16][68];
    int p  = blockIdx.y >> 1;
    int t0 = (blockIdx.y & 1) * 64;
    if (t0 >= g_vlen[p]) return;                 // fully dead t-range for this batch
    int nb = blockIdx.x * 64;
    const float* A = X + (size_t)g_perm[p] * TT * FF + (size_t)t0 * FF;

    int tid  = threadIdx.x;
    int ty   = tid >> 4, tx = tid & 15;
    int arow = tid >> 2, akk = (tid & 3) << 2;
    int bk   = tid >> 4, bn  = (tid & 15) << 2;
    float acc[4][4] = {};

    for (int k0 = 0; k0 < FF; k0 += 16) {
        float4 av = *(const float4*)(A + arow * FF + k0 + akk);
        As[akk + 0][arow] = av.x; As[akk + 1][arow] = av.y;
        As[akk + 2][arow] = av.z; As[akk + 3][arow] = av.w;
        #pragma unroll
        for (int j = 0; j < 4; j++) {
            int n = nb + bn + j;
            Bs[bk][bn + j] = (n < GATES) ? kw[(k0 + bk) * GATES + n] : 0.f;
        }
        __syncthreads();
        #pragma unroll
        for (int k = 0; k < 16; k++) {
            float4 a = *(const float4*)&As[k][ty * 4];
            float4 b = *(const float4*)&Bs[k][tx * 4];
            float avr[4] = {a.x, a.y, a.z, a.w};
            float bvr[4] = {b.x, b.y, b.z, b.w};
            #pragma unroll
            for (int i = 0; i < 4; i++)
                #pragma unroll
                for (int j = 0; j < 4; j++) acc[i][j] += avr[i] * bvr[j];
        }
        __syncthreads();
    }
    #pragma unroll
    for (int i = 0; i < 4; i++) {
        int t = t0 + ty * 4 + i;
        #pragma unroll
        for (int j = 0; j < 4; j++) {
            int g = nb + tx * 4 + j;
            if (g < GATES) {
                float bias = kb[g] + rb[g];
                if (t > 0) bias += kw[FF * GATES + g] + rw[HH * GATES + g];
                g_pre[((size_t)t * BB + p) * GATES + g] = acc[i][j] + bias;
            }
        }
    }
}

// ---------------- per-step GEMM: xo[p,:] = PRE[t,p,:] + h[p,:] @ rec_w ----------------
__global__ void k_gemm_step(const float* __restrict__ rw, int t) {
    __shared__ float As[16][68];
    __shared__ float Bs[16][68];
    int m0 = blockIdx.y * 64;
    if (m0 >= g_nact[t]) return;                 // beyond the active (sorted) prefix
    int nb = blockIdx.x * 64;

    int tid  = threadIdx.x;
    int ty   = tid >> 4, tx = tid & 15;
    int arow = tid >> 2, akk = (tid & 3) << 2;
    int bk   = tid >> 4, bn  = (tid & 15) << 2;
    float acc[4][4] = {};

    for (int k0 = 0; k0 < HH; k0 += 16) {
        float4 av = *(const float4*)(g_h + (m0 + arow) * HH + k0 + akk);
        As[akk + 0][arow] = av.x; As[akk + 1][arow] = av.y;
        As[akk + 2][arow] = av.z; As[akk + 3][arow] = av.w;
        #pragma unroll
        for (int j = 0; j < 4; j++) {
            int n = nb + bn + j;
            Bs[bk][bn + j] = (n < GATES) ? rw[(k0 + bk) * GATES + n] : 0.f;
        }
        __syncthreads();
        #pragma unroll
        for (int k = 0; k < 16; k++) {
            float4 a = *(const float4*)&As[k][ty * 4];
            float4 b = *(const float4*)&Bs[k][tx * 4];
            float avr[4] = {a.x, a.y, a.z, a.w};
            float bvr[4] = {b.x, b.y, b.z, b.w};
            #pragma unroll
            for (int i = 0; i < 4; i++)
                #pragma unroll
                for (int j = 0; j < 4; j++) acc[i][j] += avr[i] * bvr[j];
        }
        __syncthreads();
    }
    #pragma unroll
    for (int i = 0; i < 4; i++) {
        int row = m0 + ty * 4 + i;
        #pragma unroll
        for (int j = 0; j < 4; j++) {
            int g = nb + tx * 4 + j;
            if (g < GATES)
                g_xo[row * GATES + g] = acc[i][j] + g_pre[((size_t)t * BB + row) * GATES + g];
        }
    }
}

__device__ __forceinline__ float sigm(float x) { return 1.f / (1.f + expf(-x)); }

// ---------------- per-step pointwise + (final-step-only) epilogue ----------------
// grid = B blocks (sorted position p), 384 threads = (l, ch)
__global__ void k_point(const float* __restrict__ scale_w, const float* __restrict__ scale_b,
                        const float* __restrict__ rescale_w, const float* __restrict__ rescale_b,
                        const float* __restrict__ conv_b, const float* __restrict__ out_w,
                        const float* __restrict__ out_b, float* __restrict__ out, int t) {
    int p = blockIdx.x;
    if (p >= g_nact[t]) return;
    int tid = threadIdx.x;

    __shared__ float s_fm[LL], s_im[LL];
    __shared__ float s_hnew[HH];
    __shared__ float s_ldis[KW];
    __shared__ float s_lh[KW][HH];
    __shared__ float s_th[HH];
    __shared__ float s_r1[HID];
    __shared__ float s_rnn[HH];

    const float* xo = g_xo + p * GATES;
    if (tid == 0) {
        // cumax l2r over cols [0,3), cumax r2l over [3,6)
        float a0 = xo[0], a1 = xo[1], a2 = xo[2];
        float m = fmaxf(a0, fmaxf(a1, a2));
        float e0 = expf(a0 - m), e1 = expf(a1 - m), e2 = expf(a2 - m);
        float inv = 1.f / (e0 + e1 + e2);
        float fm0 = e0 * inv, fm1 = (e0 + e1) * inv, fm2 = (e0 + e1 + e2) * inv;
        s_fm[0] = fm0; s_fm[1] = fm1; s_fm[2] = fm2;
        float b0 = xo[3], b1 = xo[4], b2 = xo[5];
        float mb = fmaxf(b0, fmaxf(b1, b2));
        float f0 = expf(b0 - mb), f1 = expf(b1 - mb), f2 = expf(b2 - mb);
        float invb = 1.f / (f0 + f1 + f2);
        s_im[0] = (f0 + f1 + f2) * invb; s_im[1] = (f1 + f2) * invb; s_im[2] = f2 * invb;
        float cd = 1.f - (fm0 + fm1 + fm2) * (1.f / 3.f);
        g_tmpdis[(t % KW) * BB + p] = cd;
    }
    __syncthreads();

    int l = tid >> 7;
    float fg = sigm(xo[2 * LL + tid]);
    float ig = sigm(xo[2 * LL + HH + tid]);
    float og = sigm(xo[2 * LL + 2 * HH + tid]);
    float ci = tanhf(xo[2 * LL + 3 * HH + tid]);
    float fm = s_fm[l], im = s_im[l], ov = fm * im;
    float cl = g_c[p * HH + tid];
    float cn = ov * (fg * cl + ig * ci) + (fm - ov) * cl + (im - ov) * ci;
    float hn = og * tanhf(cn);
    g_c[p * HH + tid] = cn;
    g_h[p * HH + tid] = hn;
    g_tmph[((t % KW) * BB + p) * HH + tid] = hn;
    s_hnew[tid] = hn;

    // Expensive epilogue only at this batch's final timestep
    if (g_vlen[p] != t + 1) return;
    __syncthreads();

    if (tid == 0) {
        float buf[KW];
        float cs = 0.f;
        #pragma unroll
        for (int k = 0; k < KW; k++) {
            int s = t - (KW - 1) + k;
            float d = (s >= 0) ? g_tmpdis[(s % KW) * BB + p] : 0.f;
            cs += d;
            buf[k] = cs;
        }
        float m = buf[0];
        #pragma unroll
        for (int k = 1; k < KW; k++) m = fmaxf(m, buf[k]);
        float sum = 0.f;
        #pragma unroll
        for (int k = 0; k < KW; k++) { buf[k] = expf(buf[k] - m); sum += buf[k]; }
        float invs = 1.f / sum;
        #pragma unroll
        for (int k = 0; k < KW; k++) s_ldis[k] = buf[k] * invs;
    }
    __syncthreads();

    float tp = 0.f;
    #pragma unroll
    for (int k = 0; k < KW; k++) {
        int s = t - (KW - 1) + k;
        float hv = (s >= 0) ? g_tmph[((s % KW) * BB + p) * HH + tid] : 0.f;
        float lv = hv * s_ldis[k];
        s_lh[k][tid] = lv;
        tp += lv;
    }
    s_th[tid] = tp * (1.f / KW);
    __syncthreads();

    if (tid < HID) {
        float a = scale_b[tid];
        for (int h = 0; h < HH; h++) a += s_th[h] * scale_w[h * HID + tid];
        s_r1[tid] = fmaxf(a, 0.f);
    }
    __syncthreads();

    float th2 = rescale_b[tid];
    #pragma unroll 8
    for (int j = 0; j < HID; j++) th2 += s_r1[j] * rescale_w[j * HH + tid];
    float theme = sigm(th2);

    float cv = conv_b[tid];
    const float* ct = g_convT + tid;
    for (int hh = 0; hh < HH; hh++) {
        #pragma unroll
        for (int k = 0; k < KW; k++)
            cv += s_lh[k][hh] * ct[(hh * KW + k) * HH];
    }
    s_rnn[tid] = theme * cv + s_hnew[tid];
    __syncthreads();

    if (tid < LAB) {
        float a = out_b[tid];
        for (int h = 0; h < HH; h++) a += s_rnn[h] * out_w[h * LAB + tid];
        out[g_perm[p] * LAB + tid] = a;
    }
}

// ---------------- launch ----------------
extern "C" void kernel_launch(void* const* d_in, const int* in_sizes, int n_in,
                              void* d_out, int out_size) {
    const float* X         = (const float*)d_in[0];
    const int*   vlen      = (const int*)  d_in[1];
    const float* kw        = (const float*)d_in[2];
    const float* kb        = (const float*)d_in[3];
    const float* rw        = (const float*)d_in[4];
    const float* rb        = (const float*)d_in[5];
    const float* scale_w   = (const float*)d_in[6];
    const float* scale_b   = (const float*)d_in[7];
    const float* rescale_w = (const float*)d_in[8];
    const float* rescale_b = (const float*)d_in[9];
    const float* conv_w    = (const float*)d_in[10];
    const float* conv_b    = (const float*)d_in[11];
    const float* out_w     = (const float*)d_in[12];
    const float* out_b     = (const float*)d_in[13];
    float* out = (float*)d_out;

    k_setup<<<1, 1>>>(vlen);
    k_zero<<<(KW * BB * HH + 255) / 256, 256>>>();
    k_convT<<<(HH * HH * KW + 255) / 256, 256>>>(conv_w);

    dim3 gpre((GATES + 63) / 64, BB * 2);     // (25, 1024)
    k_gemm_pre<<<gpre, 256>>>(X, kw, kb, rw, rb);

    for (int t = 0; t < TT; t++) {
        k_gemm_step<<<dim3((GATES + 63) / 64, BB / 64), 256>>>(rw, t);
        k_point<<<BB, HH>>>(scale_w, scale_b, rescale_w, rescale_b,
                            conv_b, out_w, out_b, out, t);
    }
}

// round 4
// speedup vs baseline: 3.1363x; 3.1363x over previous
#include <cuda_runtime.h>

#define BB 512
#define TT 128
#define FF 256
#define HH 384
#define LL 3
#define KW 10
#define LAB 25
#define GATES 1542
#define HID 64
#define CONVK (HH * KW)   // 3840

// ---------------- device scratch ----------------
__device__ __align__(16) int   g_perm[BB];
__device__ __align__(16) int   g_vlen[BB];
__device__ __align__(16) int   g_nact[TT];
__device__ float g_pre[(size_t)TT * BB * GATES];              // 404 MB
__device__ float g_xo[BB * GATES];
__device__ __align__(16) float g_h[BB * HH];
__device__ __align__(16) float g_c[BB * HH];
__device__ __align__(16) float g_hist[(size_t)TT * BB * HH];  // 100 MB h history
__device__ __align__(16) float g_dish[TT * BB];
__device__ __align__(16) float g_convT[CONVK * HH];           // [(hh*KW+k)][o]
__device__ __align__(16) float g_lh[BB * CONVK];
__device__ __align__(16) float g_theme[BB * HH];
__device__ __align__(16) float g_conv[BB * HH];

__device__ __forceinline__ float sigm(float x) { return 1.f / (1.f + expf(-x)); }

// ---------------- setup: stable counting sort by v_len descending ----------------
__global__ void k_setup(const int* __restrict__ vlen) {
    int cnt[129];
    for (int v = 0; v <= 128; v++) cnt[v] = 0;
    for (int b = 0; b < BB; b++) cnt[vlen[b]]++;
    int cur[129];
    int off = 0;
    for (int v = 128; v >= 1; v--) { cur[v] = off; off += cnt[v]; }
    for (int b = 0; b < BB; b++) {
        int v = vlen[b];
        int p = cur[v]++;
        g_perm[p] = b;
        g_vlen[p] = v;
    }
    int suf = 0;
    for (int t = TT - 1; t >= 0; t--) { suf += cnt[t + 1]; g_nact[t] = suf; }
}

__global__ void k_zero() {
    int i = blockIdx.x * blockDim.x + threadIdx.x;
    if (i < BB * HH) { g_h[i] = 0.f; g_c[i] = 0.f; }
}

__global__ void k_convT(const float* __restrict__ cw) {
    int i = blockIdx.x * blockDim.x + threadIdx.x;
    if (i >= HH * HH * KW) return;
    int k  = i % KW;
    int hh = (i / KW) % HH;
    int o  = i / (KW * HH);
    g_convT[(hh * KW + k) * HH + o] = cw[i];
}

// ---------------- precompute GEMM: PRE[t,p,:] = X[perm[p],t,:] @ kw + biases ----------------
__global__ void k_gemm_pre(const float* __restrict__ X, const float* __restrict__ kw,
                           const float* __restrict__ kb, const float* __restrict__ rw,
                           const float* __restrict__ rb) {
    __shared__ float As[16][68];
    __shared__ float Bs[16][68];
    int p  = blockIdx.y >> 1;
    int t0 = (blockIdx.y & 1) * 64;
    if (t0 >= g_vlen[p]) return;
    int nb = blockIdx.x * 64;
    const float* A = X + (size_t)g_perm[p] * TT * FF + (size_t)t0 * FF;

    int tid  = threadIdx.x;
    int ty   = tid >> 4, tx = tid & 15;
    int arow = tid >> 2, akk = (tid & 3) << 2;
    int bk   = tid >> 4, bn  = (tid & 15) << 2;
    float acc[4][4] = {};

    float4 a_nxt = *(const float4*)(A + arow * FF + akk);
    float b_nxt[4];
    #pragma unroll
    for (int j = 0; j < 4; j++) {
        int n = nb + bn + j;
        b_nxt[j] = (n < GATES) ? kw[bk * GATES + n] : 0.f;
    }

    for (int k0 = 0; k0 < FF; k0 += 16) {
        As[akk + 0][arow] = a_nxt.x; As[akk + 1][arow] = a_nxt.y;
        As[akk + 2][arow] = a_nxt.z; As[akk + 3][arow] = a_nxt.w;
        #pragma unroll
        for (int j = 0; j < 4; j++) Bs[bk][bn + j] = b_nxt[j];
        __syncthreads();
        if (k0 + 16 < FF) {
            a_nxt = *(const float4*)(A + arow * FF + k0 + 16 + akk);
            #pragma unroll
            for (int j = 0; j < 4; j++) {
                int n = nb + bn + j;
                b_nxt[j] = (n < GATES) ? kw[(k0 + 16 + bk) * GATES + n] : 0.f;
            }
        }
        #pragma unroll
        for (int k = 0; k < 16; k++) {
            float4 a = *(const float4*)&As[k][ty * 4];
            float4 b = *(const float4*)&Bs[k][tx * 4];
            float avr[4] = {a.x, a.y, a.z, a.w};
            float bvr[4] = {b.x, b.y, b.z, b.w};
            #pragma unroll
            for (int i = 0; i < 4; i++)
                #pragma unroll
                for (int j = 0; j < 4; j++) acc[i][j] += avr[i] * bvr[j];
        }
        __syncthreads();
    }
    #pragma unroll
    for (int i = 0; i < 4; i++) {
        int t = t0 + ty * 4 + i;
        #pragma unroll
        for (int j = 0; j < 4; j++) {
            int g = nb + tx * 4 + j;
            if (g < GATES) {
                float bias = kb[g] + rb[g];
                if (t > 0) bias += kw[FF * GATES + g] + rw[HH * GATES + g];
                g_pre[((size_t)t * BB + p) * GATES + g] = acc[i][j] + bias;
            }
        }
    }
}

// ---------------- per-step GEMM: xo[p,:] = h[p,:] @ rec_w + PRE[t,p,:] ----------------
__global__ void k_gemm_step(const float* __restrict__ rw, int t) {
    __shared__ float As[16][68];
    __shared__ float Bs[16][68];
    int m0 = blockIdx.y * 64;
    if (m0 >= g_nact[t]) return;
    int nb = blockIdx.x * 64;

    int tid  = threadIdx.x;
    int ty   = tid >> 4, tx = tid & 15;
    int arow = tid >> 2, akk = (tid & 3) << 2;
    int bk   = tid >> 4, bn  = (tid & 15) << 2;
    float acc[4][4] = {};
    const float* A = g_h + m0 * HH;

    float4 a_nxt = *(const float4*)(A + arow * HH + akk);
    float b_nxt[4];
    #pragma unroll
    for (int j = 0; j < 4; j++) {
        int n = nb + bn + j;
        b_nxt[j] = (n < GATES) ? rw[bk * GATES + n] : 0.f;
    }
    for (int k0 = 0; k0 < HH; k0 += 16) {
        As[akk + 0][arow] = a_nxt.x; As[akk + 1][arow] = a_nxt.y;
        As[akk + 2][arow] = a_nxt.z; As[akk + 3][arow] = a_nxt.w;
        #pragma unroll
        for (int j = 0; j < 4; j++) Bs[bk][bn + j] = b_nxt[j];
        __syncthreads();
        if (k0 + 16 < HH) {
            a_nxt = *(const float4*)(A + arow * HH + k0 + 16 + akk);
            #pragma unroll
            for (int j = 0; j < 4; j++) {
                int n = nb + bn + j;
                b_nxt[j] = (n < GATES) ? rw[(k0 + 16 + bk) * GATES + n] : 0.f;
            }
        }
        #pragma unroll
        for (int k = 0; k < 16; k++) {
            float4 a = *(const float4*)&As[k][ty * 4];
            float4 b = *(const float4*)&Bs[k][tx * 4];
            float avr[4] = {a.x, a.y, a.z, a.w};
            float bvr[4] = {b.x, b.y, b.z, b.w};
            #pragma unroll
            for (int i = 0; i < 4; i++)
                #pragma unroll
                for (int j = 0; j < 4; j++) acc[i][j] += avr[i] * bvr[j];
        }
        __syncthreads();
    }
    const float* pre = g_pre + (size_t)t * BB * GATES;
    #pragma unroll
    for (int i = 0; i < 4; i++) {
        int row = m0 + ty * 4 + i;
        #pragma unroll
        for (int j = 0; j < 4; j++) {
            int g = nb + tx * 4 + j;
            if (g < GATES)
                g_xo[row * GATES + g] = acc[i][j] + pre[(size_t)row * GATES + g];
        }
    }
}

// ---------------- per-step pointwise LSTM update (no epilogue) ----------------
__global__ void k_point(int t) {
    int p = blockIdx.x;
    if (p >= g_nact[t]) return;
    int tid = threadIdx.x;
    __shared__ float s_fm[LL], s_im[LL];

    const float* xo = g_xo + p * GATES;
    if (tid == 0) {
        float a0 = xo[0], a1 = xo[1], a2 = xo[2];
        float m = fmaxf(a0, fmaxf(a1, a2));
        float e0 = expf(a0 - m), e1 = expf(a1 - m), e2 = expf(a2 - m);
        float inv = 1.f / (e0 + e1 + e2);
        float fm0 = e0 * inv, fm1 = (e0 + e1) * inv, fm2 = (e0 + e1 + e2) * inv;
        s_fm[0] = fm0; s_fm[1] = fm1; s_fm[2] = fm2;
        float b0 = xo[3], b1 = xo[4], b2 = xo[5];
        float mb = fmaxf(b0, fmaxf(b1, b2));
        float f0 = expf(b0 - mb), f1 = expf(b1 - mb), f2 = expf(b2 - mb);
        float invb = 1.f / (f0 + f1 + f2);
        s_im[0] = (f0 + f1 + f2) * invb; s_im[1] = (f1 + f2) * invb; s_im[2] = f2 * invb;
        g_dish[t * BB + p] = 1.f - (fm0 + fm1 + fm2) * (1.f / 3.f);
    }
    __syncthreads();

    int l = tid >> 7;
    float fg = sigm(xo[2 * LL + tid]);
    float ig = sigm(xo[2 * LL + HH + tid]);
    float og = sigm(xo[2 * LL + 2 * HH + tid]);
    float ci = tanhf(xo[2 * LL + 3 * HH + tid]);
    float fm = s_fm[l], im = s_im[l], ov = fm * im;
    float cl = g_c[p * HH + tid];
    float cn = ov * (fg * cl + ig * ci) + (fm - ov) * cl + (im - ov) * ci;
    float hn = og * tanhf(cn);
    g_c[p * HH + tid] = cn;
    g_h[p * HH + tid] = hn;
    g_hist[((size_t)t * BB + p) * HH + tid] = hn;
}

// ---------------- batched epilogue (after loop) ----------------
__global__ void k_fin1(const float* __restrict__ scale_w, const float* __restrict__ scale_b,
                       const float* __restrict__ rescale_w, const float* __restrict__ rescale_b) {
    int p = blockIdx.x;
    int tl = g_vlen[p] - 1;
    int tid = threadIdx.x;
    __shared__ float s_ldis[KW];
    __shared__ float s_th[HH];
    __shared__ float s_r1[HID];

    if (tid == 0) {
        float buf[KW];
        float cs = 0.f;
        #pragma unroll
        for (int k = 0; k < KW; k++) {
            int s = tl - (KW - 1) + k;
            cs += (s >= 0) ? g_dish[s * BB + p] : 0.f;
            buf[k] = cs;
        }
        float m = buf[0];
        #pragma unroll
        for (int k = 1; k < KW; k++) m = fmaxf(m, buf[k]);
        float sum = 0.f;
        #pragma unroll
        for (int k = 0; k < KW; k++) { buf[k] = expf(buf[k] - m); sum += buf[k]; }
        float invs = 1.f / sum;
        #pragma unroll
        for (int k = 0; k < KW; k++) s_ldis[k] = buf[k] * invs;
    }
    __syncthreads();

    for (int e = tid; e < HH; e += 256) {
        float tp = 0.f;
        #pragma unroll
        for (int k = 0; k < KW; k++) {
            int s = tl - (KW - 1) + k;
            float hv = (s >= 0) ? g_hist[((size_t)s * BB + p) * HH + e] : 0.f;
            float lv = hv * s_ldis[k];
            g_lh[(size_t)p * CONVK + e * KW + k] = lv;
            tp += lv;
        }
        s_th[e] = tp * (1.f / KW);
    }
    __syncthreads();

    if (tid < HID) {
        float a = scale_b[tid];
        for (int h = 0; h < HH; h++) a += s_th[h] * scale_w[h * HID + tid];
        s_r1[tid] = fmaxf(a, 0.f);
    }
    __syncthreads();

    for (int e = tid; e < HH; e += 256) {
        float th2 = rescale_b[e];
        #pragma unroll 8
        for (int j = 0; j < HID; j++) th2 += s_r1[j] * rescale_w[j * HH + e];
        g_theme[p * HH + e] = sigm(th2);
    }
}

// fin2: conv GEMM  g_conv[512,384] = g_lh[512,3840] @ g_convT[3840,384]
__global__ void k_fin2() {
    __shared__ float As[16][68];
    __shared__ float Bs[16][68];
    int m0 = blockIdx.y * 64;
    int nb = blockIdx.x * 64;
    int tid  = threadIdx.x;
    int ty   = tid >> 4, tx = tid & 15;
    int arow = tid >> 2, akk = (tid & 3) << 2;
    int bk   = tid >> 4, bn  = (tid & 15) << 2;
    float acc[4][4] = {};
    const float* A = g_lh + (size_t)m0 * CONVK;

    float4 a_nxt = *(const float4*)(A + (size_t)arow * CONVK + akk);
    float4 b_nxt = *(const float4*)(g_convT + bk * HH + nb + bn);

    for (int k0 = 0; k0 < CONVK; k0 += 16) {
        As[akk + 0][arow] = a_nxt.x; As[akk + 1][arow] = a_nxt.y;
        As[akk + 2][arow] = a_nxt.z; As[akk + 3][arow] = a_nxt.w;
        *(float4*)&Bs[bk][bn] = b_nxt;
        __syncthreads();
        if (k0 + 16 < CONVK) {
            a_nxt = *(const float4*)(A + (size_t)arow * CONVK + k0 + 16 + akk);
            b_nxt = *(const float4*)(g_convT + (k0 + 16 + bk) * HH + nb + bn);
        }
        #pragma unroll
        for (int k = 0; k < 16; k++) {
            float4 a = *(const float4*)&As[k][ty * 4];
            float4 b = *(const float4*)&Bs[k][tx * 4];
            float avr[4] = {a.x, a.y, a.z, a.w};
            float bvr[4] = {b.x, b.y, b.z, b.w};
            #pragma unroll
            for (int i = 0; i < 4; i++)
                #pragma unroll
                for (int j = 0; j < 4; j++) acc[i][j] += avr[i] * bvr[j];
        }
        __syncthreads();
    }
    #pragma unroll
    for (int i = 0; i < 4; i++)
        #pragma unroll
        for (int j = 0; j < 4; j++)
            g_conv[(m0 + ty * 4 + i) * HH + nb + tx * 4 + j] = acc[i][j];
}

// fin3: rnn = theme*(conv+conv_b) + h_final; out = rnn @ out_w + out_b (scatter by perm)
__global__ void k_fin3(const float* __restrict__ conv_b, const float* __restrict__ out_w,
                       const float* __restrict__ out_b, float* __restrict__ out) {
    int p = blockIdx.x;
    int tid = threadIdx.x;
    int tl = g_vlen[p] - 1;
    __shared__ float s_rnn[HH];
    s_rnn[tid] = g_theme[p * HH + tid] * (g_conv[p * HH + tid] + conv_b[tid])
               + g_hist[((size_t)tl * BB + p) * HH + tid];
    __syncthreads();
    if (tid < LAB) {
        float a = out_b[tid];
        for (int h = 0; h < HH; h++) a += s_rnn[h] * out_w[h * LAB + tid];
        out[g_perm[p] * LAB + tid] = a;
    }
}

// ---------------- launch ----------------
extern "C" void kernel_launch(void* const* d_in, const int* in_sizes, int n_in,
                              void* d_out, int out_size) {
    const float* X         = (const float*)d_in[0];
    const int*   vlen      = (const int*)  d_in[1];
    const float* kw        = (const float*)d_in[2];
    const float* kb        = (const float*)d_in[3];
    const float* rw        = (const float*)d_in[4];
    const float* rb        = (const float*)d_in[5];
    const float* scale_w   = (const float*)d_in[6];
    const float* scale_b   = (const float*)d_in[7];
    const float* rescale_w = (const float*)d_in[8];
    const float* rescale_b = (const float*)d_in[9];
    const float* conv_w    = (const float*)d_in[10];
    const float* conv_b    = (const float*)d_in[11];
    const float* out_w     = (const float*)d_in[12];
    const float* out_b     = (const float*)d_in[13];
    float* out = (float*)d_out;

    k_setup<<<1, 1>>>(vlen);
    k_zero<<<(BB * HH + 255) / 256, 256>>>();
    k_convT<<<(HH * HH * KW + 255) / 256, 256>>>(conv_w);

    k_gemm_pre<<<dim3(25, BB * 2), 256>>>(X, kw, kb, rw, rb);

    for (int t = 0; t < TT; t++) {
        k_gemm_step<<<dim3(25, BB / 64), 256>>>(rw, t);
        k_point<<<BB, HH>>>(t);
    }

    k_fin1<<<BB, 256>>>(scale_w, scale_b, rescale_w, rescale_b);
    k_fin2<<<dim3(HH / 64, BB / 64), 256>>>();
    k_fin3<<<BB, HH>>>(conv_b, out_w, out_b, out);
}